// round 16
// baseline (speedup 1.0000x reference)
#include <cuda_runtime.h>
#include <cuda_bf16.h>
#include <math_constants.h>
#include <cstdint>

// Problem shape (fixed)
#define B_  2
#define S_  4096
#define D_  768
#define H_  12
#define DH_ 64
#define MROWS (B_ * S_)          // 8192

// Scratch (allocation-free __device__ globals)
__device__ float g_q[B_ * H_ * S_ * DH_];
__device__ __align__(16) __nv_bfloat16 g_hhi [MROWS * D_];
__device__ __align__(16) __nv_bfloat16 g_hlo [MROWS * D_];
__device__ __align__(16) __nv_bfloat16 g_whi [4 * D_ * D_];   // Wq,Wk,Wv,Wo
__device__ __align__(16) __nv_bfloat16 g_wlo [4 * D_ * D_];
__device__ __align__(16) __nv_bfloat16 g_khi [B_ * H_ * S_ * DH_];
__device__ __align__(16) __nv_bfloat16 g_klo [B_ * H_ * S_ * DH_];
__device__ __align__(16) __nv_bfloat16 g_vthi[B_ * H_ * S_ * DH_];
__device__ __align__(16) __nv_bfloat16 g_vtlo[B_ * H_ * S_ * DH_];
__device__ __align__(16) __nv_bfloat16 g_atthi[MROWS * D_];
__device__ __align__(16) __nv_bfloat16 g_attlo[MROWS * D_];

// ---------------------------------------------------------------------------
// bf16 3-term decomposition helpers
// ---------------------------------------------------------------------------
__device__ __forceinline__ void split_bf16(float x, __nv_bfloat16& h, __nv_bfloat16& l) {
    h = __float2bfloat16_rn(x);
    l = __float2bfloat16_rn(x - __bfloat162float(h));
}
__device__ __forceinline__ uint32_t bpack(__nv_bfloat16 a, __nv_bfloat16 b) {
    return (uint32_t)__bfloat16_as_ushort(a) | ((uint32_t)__bfloat16_as_ushort(b) << 16);
}
__device__ __forceinline__ void mma16(float c[4], const uint32_t a[4],
                                      uint32_t b0, uint32_t b1) {
    asm volatile(
        "mma.sync.aligned.m16n8k16.row.col.f32.bf16.bf16.f32 "
        "{%0,%1,%2,%3}, {%4,%5,%6,%7}, {%8,%9}, {%0,%1,%2,%3};"
        : "+f"(c[0]), "+f"(c[1]), "+f"(c[2]), "+f"(c[3])
        : "r"(a[0]), "r"(a[1]), "r"(a[2]), "r"(a[3]), "r"(b0), "r"(b1));
}
__device__ __forceinline__ void mma3(float c[4],
                                     const uint32_t ah[4], const uint32_t al[4],
                                     uint32_t bh0, uint32_t bh1,
                                     uint32_t bl0, uint32_t bl1) {
    mma16(c, ah, bh0, bh1);
    mma16(c, ah, bl0, bl1);
    mma16(c, al, bh0, bh1);
}

// ldmatrix x4: four 8x8 b16 matrices; lane l supplies row (l&7) of matrix l>>3.
__device__ __forceinline__ void ldsm4(uint32_t r[4], uint32_t addr) {
    asm volatile("ldmatrix.sync.aligned.m8n8.x4.shared.b16 {%0,%1,%2,%3}, [%4];"
                 : "=r"(r[0]), "=r"(r[1]), "=r"(r[2]), "=r"(r[3]) : "r"(addr));
}

// cp.async: 16B gmem -> smem (LDGSTS).
__device__ __forceinline__ void cp16(__nv_bfloat16* dst, const __nv_bfloat16* src) {
    uint32_t s = (uint32_t)__cvta_generic_to_shared(dst);
    asm volatile("cp.async.cg.shared.global [%0], [%1], 16;"
                 :: "r"(s), "l"(src) : "memory");
}
#define CP_COMMIT() asm volatile("cp.async.commit_group;" ::: "memory")
#define CP_WAIT0()  asm volatile("cp.async.wait_group 0;"  ::: "memory")

#define PADB 72      // bf16 row stride (144 B = 9*16B: LDSM conflict-free)
#define ROWB (PADB * 2)   // bytes

// ---------------------------------------------------------------------------
// Fused one-shot splitter: h + Wq + Wk + Wv + Wo -> bf16 hi/lo planes in a
// single launch. Segment chosen by index range (compile-time prefix sums).
// ---------------------------------------------------------------------------
#define NH_ (MROWS * D_)     // 6291456
#define NW_ (D_ * D_)        // 589824
#define NTOT_ (NH_ + 4 * NW_)

__device__ __forceinline__ void split4(const float* __restrict__ src,
                                       __nv_bfloat16* __restrict__ hi,
                                       __nv_bfloat16* __restrict__ lo, int i)
{
    float4 v = *(const float4*)(src + i);
    __nv_bfloat16 h0,l0,h1,l1,h2,l2,h3,l3;
    split_bf16(v.x, h0, l0); split_bf16(v.y, h1, l1);
    split_bf16(v.z, h2, l2); split_bf16(v.w, h3, l3);
    *(uint32_t*)(hi + i)     = bpack(h0, h1);
    *(uint32_t*)(hi + i + 2) = bpack(h2, h3);
    *(uint32_t*)(lo + i)     = bpack(l0, l1);
    *(uint32_t*)(lo + i + 2) = bpack(l2, l3);
}

__global__ void split_all_kernel(
    const float* __restrict__ h,
    const float* __restrict__ Wq, const float* __restrict__ Wk,
    const float* __restrict__ Wv, const float* __restrict__ Wo,
    __nv_bfloat16* __restrict__ hhi, __nv_bfloat16* __restrict__ hlo,
    __nv_bfloat16* __restrict__ whi, __nv_bfloat16* __restrict__ wlo)
{
    const int gi = (blockIdx.x * blockDim.x + threadIdx.x) * 4;
    if (gi >= NTOT_) return;
    if (gi < NH_) {
        split4(h, hhi, hlo, gi);
    } else {
        const int wi = gi - NH_;
        const int z  = wi / NW_;             // 0..3 (all 4 ranges NW_-aligned)
        const int li = wi - z * NW_;
        const float* src = (z == 0) ? Wq : (z == 1) ? Wk : (z == 2) ? Wv : Wo;
        split4(src, whi + (size_t)z * NW_, wlo + (size_t)z * NW_, li);
    }
}

// ---------------------------------------------------------------------------
// Shared projection GEMM body (NT), bf16 3-term, cp.async double-buffered,
// LDSM fragments.
// ---------------------------------------------------------------------------
#define ABUF (128 * PADB)
#define WBUF (64 * PADB)
#define PROJ_SMEM_BYTES ((2 * ABUF + 2 * WBUF) * 2 * 2)

__device__ __forceinline__ void proj_body(
    const __nv_bfloat16* __restrict__ Ahg, const __nv_bfloat16* __restrict__ Alg,
    const __nv_bfloat16* __restrict__ Whg, const __nv_bfloat16* __restrict__ Wlg,
    const float* __restrict__ bias,
    float* __restrict__ Cf,
    __nv_bfloat16* __restrict__ Chi, __nv_bfloat16* __restrict__ Clo,
    int K, int mode, float scale, __nv_bfloat16* smb)
{
    __nv_bfloat16* Ah = smb;                 // [2][ABUF]
    __nv_bfloat16* Al = Ah + 2 * ABUF;
    __nv_bfloat16* Wh = Al + 2 * ABUF;       // [2][WBUF]
    __nv_bfloat16* Wl = Wh + 2 * WBUF;

    const int tid  = threadIdx.x;
    const int mw   = tid >> 5;
    const int lane = tid & 31;
    const int quad = lane >> 2;
    const int tq   = lane & 3;
    const int m0 = blockIdx.y * 128;
    const int n0 = blockIdx.x * 64;

    const int r0 = 16 * mw + quad;
    const int r1 = r0 + 8;

    const int arow = tid >> 1, aseg = (tid & 1) * 32;
    const int wrow = tid >> 2, wseg = (tid & 3) * 16;
    const int adst = arow * PADB + aseg;
    const int wdst = wrow * PADB + wseg;
    const __nv_bfloat16* ahs = Ahg + (size_t)(m0 + arow) * K + aseg;
    const __nv_bfloat16* als = Alg + (size_t)(m0 + arow) * K + aseg;
    const __nv_bfloat16* whs = Whg + (size_t)(n0 + wrow) * K + wseg;
    const __nv_bfloat16* wls = Wlg + (size_t)(n0 + wrow) * K + wseg;

    auto issue_chunk = [&](int kc, int bsel) {
#pragma unroll
        for (int u = 0; u < 4; u++) {
            cp16(Ah + bsel * ABUF + adst + 8 * u, ahs + kc + 8 * u);
            cp16(Al + bsel * ABUF + adst + 8 * u, als + kc + 8 * u);
        }
#pragma unroll
        for (int u = 0; u < 2; u++) {
            cp16(Wh + bsel * WBUF + wdst + 8 * u, whs + kc + 8 * u);
            cp16(Wl + bsel * WBUF + wdst + 8 * u, wls + kc + 8 * u);
        }
        CP_COMMIT();
    };

    const int g = lane >> 3, r8 = lane & 7;
    const uint32_t offA = (uint32_t)((16 * mw + (g & 1) * 8 + r8) * ROWB + (g >> 1) * 16);
    const uint32_t offB = (uint32_t)(((g >> 1) * 8 + r8) * ROWB + (g & 1) * 16);
    const uint32_t ah_s = (uint32_t)__cvta_generic_to_shared(Ah) + offA;
    const uint32_t al_s = (uint32_t)__cvta_generic_to_shared(Al) + offA;
    const uint32_t wh_s = (uint32_t)__cvta_generic_to_shared(Wh) + offB;
    const uint32_t wl_s = (uint32_t)__cvta_generic_to_shared(Wl) + offB;

    float accC[8][4];
#pragma unroll
    for (int nt = 0; nt < 8; nt++)
#pragma unroll
        for (int j = 0; j < 4; j++) accC[nt][j] = 0.0f;

    issue_chunk(0, 0);
    CP_WAIT0();
    __syncthreads();

    const int NCH = K / 64;
    for (int t = 0; t < NCH; t++) {
        const int cur = t & 1;
        const uint32_t ac = ah_s + cur * (ABUF * 2);
        const uint32_t lc = al_s + cur * (ABUF * 2);
        const uint32_t wc = wh_s + cur * (WBUF * 2);
        const uint32_t xc = wl_s + cur * (WBUF * 2);

        const bool more = (t + 1 < NCH);
        if (more) issue_chunk((t + 1) * 64, 1 - cur);

#pragma unroll
        for (int ks = 0; ks < 4; ks++) {
            uint32_t a_h[4], a_l[4];
            ldsm4(a_h, ac + 32 * ks);
            ldsm4(a_l, lc + 32 * ks);
#pragma unroll
            for (int np = 0; np < 4; np++) {
                uint32_t b_h[4], b_l[4];
                ldsm4(b_h, wc + np * (16 * ROWB) + 32 * ks);
                ldsm4(b_l, xc + np * (16 * ROWB) + 32 * ks);
                mma3(accC[2 * np],     a_h, a_l, b_h[0], b_h[1], b_l[0], b_l[1]);
                mma3(accC[2 * np + 1], a_h, a_l, b_h[2], b_h[3], b_l[2], b_l[3]);
            }
        }

        if (more) CP_WAIT0();
        __syncthreads();
    }

    // epilogue
#pragma unroll
    for (int nt = 0; nt < 8; nt++) {
        const int n = n0 + 8 * nt + 2 * tq;
        const float b0v = bias[n], b1v = bias[n + 1];
#pragma unroll
        for (int half = 0; half < 2; half++) {
            const int m = m0 + (half ? r1 : r0);
            float v0 = (accC[nt][2 * half + 0] + b0v) * scale;
            float v1 = (accC[nt][2 * half + 1] + b1v) * scale;
            if (mode == 0) {
                *(float2*)(Cf + (size_t)m * D_ + n) = make_float2(v0, v1);
            } else {
                const int bb = m >> 12, s = m & (S_ - 1);
                const int hh = n >> 6,  d = n & (DH_ - 1);
                if (mode == 1) {
                    const size_t idx = (((size_t)bb * H_ + hh) * S_ + s) * DH_ + d;
                    *(float2*)(Cf + idx) = make_float2(v0, v1);
                } else if (mode == 2) {
                    const size_t idx = (((size_t)bb * H_ + hh) * S_ + s) * DH_ + d;
                    __nv_bfloat16 h0,l0,h1,l1;
                    split_bf16(v0, h0, l0); split_bf16(v1, h1, l1);
                    *(uint32_t*)(Chi + idx) = bpack(h0, h1);
                    *(uint32_t*)(Clo + idx) = bpack(l0, l1);
                } else {   // mode 3: transposed [B,H,DH,S]
                    const size_t tix = (((size_t)bb * H_ + hh) * DH_ + d) * S_ + s;
                    __nv_bfloat16 h0,l0,h1,l1;
                    split_bf16(v0, h0, l0); split_bf16(v1, h1, l1);
                    Chi[tix] = h0; Chi[tix + S_] = h1;
                    Clo[tix] = l0; Clo[tix + S_] = l1;
                }
            }
        }
    }
}

// Fused QKV projection: gridDim.z = 3 selects Q/K/V (shared A = split h).
__global__ __launch_bounds__(256) void qkv_mma_kernel(
    const __nv_bfloat16* __restrict__ Ahg, const __nv_bfloat16* __restrict__ Alg,
    const __nv_bfloat16* __restrict__ Wall_h, const __nv_bfloat16* __restrict__ Wall_l,
    const float* __restrict__ bq, const float* __restrict__ bk,
    const float* __restrict__ bv,
    float* __restrict__ qout,
    __nv_bfloat16* __restrict__ khi, __nv_bfloat16* __restrict__ klo,
    __nv_bfloat16* __restrict__ vhi, __nv_bfloat16* __restrict__ vlo)
{
    extern __shared__ __nv_bfloat16 smb[];
    const int z = blockIdx.z;
    const __nv_bfloat16* Wh = Wall_h + (size_t)z * NW_;
    const __nv_bfloat16* Wl = Wall_l + (size_t)z * NW_;
    const float* bias = (z == 0) ? bq : (z == 1) ? bk : bv;
    float* Cf = (z == 0) ? qout : nullptr;
    __nv_bfloat16* Chi = (z == 1) ? khi : (z == 2) ? vhi : nullptr;
    __nv_bfloat16* Clo = (z == 1) ? klo : (z == 2) ? vlo : nullptr;
    const int mode = z + 1;
    const float scale = (z == 0) ? 0.125f : 1.0f;
    proj_body(Ahg, Alg, Wh, Wl, bias, Cf, Chi, Clo, D_, mode, scale, smb);
}

// Output projection (Wo), mode 0.
__global__ __launch_bounds__(256) void proj_mma_kernel(
    const __nv_bfloat16* __restrict__ Ahg, const __nv_bfloat16* __restrict__ Alg,
    const __nv_bfloat16* __restrict__ Whg, const __nv_bfloat16* __restrict__ Wlg,
    const float* __restrict__ bias, float* __restrict__ Cf)
{
    extern __shared__ __nv_bfloat16 smb[];
    proj_body(Ahg, Alg, Whg, Wlg, bias, Cf, nullptr, nullptr, D_, 0, 1.0f, smb);
}

// ---------------------------------------------------------------------------
// Flash attention, bf16 3-term, cp.async double-buffered K/V, LDSM fragments.
// P and Q fragments REGISTER-RESIDENT.
// ---------------------------------------------------------------------------
#define KVBUF (64 * PADB)
#define ATTN_SMEM_BYTES ((2*128*PADB + 8*KVBUF) * 2 + 2 * 64 * 4)

__global__ __launch_bounds__(256) void attn_mma_kernel(
    const float* __restrict__ q,
    const __nv_bfloat16* __restrict__ khi, const __nv_bfloat16* __restrict__ klo,
    const __nv_bfloat16* __restrict__ vthi, const __nv_bfloat16* __restrict__ vtlo,
    const int* __restrict__ mask,
    __nv_bfloat16* __restrict__ atthi, __nv_bfloat16* __restrict__ attlo)
{
    extern __shared__ __nv_bfloat16 smb[];
    __nv_bfloat16* Qh = smb;                       // [128][PADB]
    __nv_bfloat16* Ql = Qh + 128 * PADB;
    __nv_bfloat16* Kh = Ql + 128 * PADB;           // [2][64][PADB]
    __nv_bfloat16* Kl = Kh + 2 * KVBUF;
    __nv_bfloat16* Vh = Kl + 2 * KVBUF;            // [2][64][PADB] (transposed)
    __nv_bfloat16* Vl = Vh + 2 * KVBUF;
    float* Mk = (float*)(Vl + 2 * KVBUF);          // [2][64]

    const int tid  = threadIdx.x;
    const int mw   = tid >> 5;
    const int lane = tid & 31;
    const int quad = lane >> 2;
    const int tq   = lane & 3;
    const int bh = blockIdx.y;
    const int b  = bh / H_;
    const int hh = bh - b * H_;
    const int q0 = blockIdx.x * 128;

    const size_t hoff = (size_t)bh * S_ * DH_;
    const float* qb = q + hoff;
    const int*   mb = mask + b * S_;

    const int r0 = 16 * mw + quad;
    const int r1 = r0 + 8;

    const int lrow8 = 8 * mw + (lane & 7);
    const int lseg  = (lane >> 3) * 16;
    const int sdst  = lrow8 * PADB + lseg;
    const __nv_bfloat16* khg = khi  + hoff + (size_t)lrow8 * DH_ + lseg;
    const __nv_bfloat16* klg = klo  + hoff + (size_t)lrow8 * DH_ + lseg;
    const __nv_bfloat16* vhg = vthi + hoff + (size_t)lrow8 * S_ + lseg;
    const __nv_bfloat16* vlg = vtlo + hoff + (size_t)lrow8 * S_ + lseg;

    auto issue_tile = [&](int t, int bsel) {
        const size_t ko = (size_t)t * 64 * DH_;
        const size_t vo = (size_t)t * 64;
        cp16(Kh + bsel * KVBUF + sdst,     khg + ko);
        cp16(Kh + bsel * KVBUF + sdst + 8, khg + ko + 8);
        cp16(Kl + bsel * KVBUF + sdst,     klg + ko);
        cp16(Kl + bsel * KVBUF + sdst + 8, klg + ko + 8);
        cp16(Vh + bsel * KVBUF + sdst,     vhg + vo);
        cp16(Vh + bsel * KVBUF + sdst + 8, vhg + vo + 8);
        cp16(Vl + bsel * KVBUF + sdst,     vlg + vo);
        cp16(Vl + bsel * KVBUF + sdst + 8, vlg + vo + 8);
        CP_COMMIT();
    };

    // LDSM per-lane offsets
    const int g = lane >> 3, r8 = lane & 7;
    const uint32_t offA = (uint32_t)((16 * mw + (g & 1) * 8 + r8) * ROWB + (g >> 1) * 16);
    const uint32_t offB = (uint32_t)(((g >> 1) * 8 + r8) * ROWB + (g & 1) * 16);
    const uint32_t qh_s = (uint32_t)__cvta_generic_to_shared(Qh) + offA;
    const uint32_t ql_s = (uint32_t)__cvta_generic_to_shared(Ql) + offA;
    const uint32_t kh_s = (uint32_t)__cvta_generic_to_shared(Kh) + offB;
    const uint32_t kl_s = (uint32_t)__cvta_generic_to_shared(Kl) + offB;
    const uint32_t vh_s = (uint32_t)__cvta_generic_to_shared(Vh) + offB;
    const uint32_t vl_s = (uint32_t)__cvta_generic_to_shared(Vl) + offB;

    issue_tile(0, 0);
    int mreg = (tid < 64) ? mb[tid] : 0;
    {
        const int row = tid >> 1, colb = (tid & 1) * 32;
#pragma unroll
        for (int u = 0; u < 8; u++) {
            const int c = colb + 4 * u;
            float4 qv = *(const float4*)(qb + (size_t)(q0 + row) * DH_ + c);
            __nv_bfloat16 h0,l0,h1,l1,h2,l2,h3,l3;
            split_bf16(qv.x, h0, l0); split_bf16(qv.y, h1, l1);
            split_bf16(qv.z, h2, l2); split_bf16(qv.w, h3, l3);
            *(uint32_t*)(Qh + row * PADB + c)     = bpack(h0, h1);
            *(uint32_t*)(Qh + row * PADB + c + 2) = bpack(h2, h3);
            *(uint32_t*)(Ql + row * PADB + c)     = bpack(l0, l1);
            *(uint32_t*)(Ql + row * PADB + c + 2) = bpack(l2, l3);
        }
    }
    CP_WAIT0();
    if (tid < 64) Mk[tid] = (float)mreg;   // Mk[0]
    __syncthreads();

    // ---- hoist Q fragments into registers (loop-invariant) ----
    uint32_t aQh[4][4], aQl[4][4];
#pragma unroll
    for (int ks = 0; ks < 4; ks++) {
        ldsm4(aQh[ks], qh_s + 32 * ks);
        ldsm4(aQl[ks], ql_s + 32 * ks);
    }

    float m0r = -CUDART_INF_F, m1r = -CUDART_INF_F;
    float l0r = 0.0f, l1r = 0.0f;
    float accO[8][4];
#pragma unroll
    for (int nt = 0; nt < 8; nt++)
#pragma unroll
        for (int j = 0; j < 4; j++) accO[nt][j] = 0.0f;

    for (int t = 0; t < S_ / 64; t++) {
        const int cur = t & 1;
        const uint32_t khc = kh_s + cur * (KVBUF * 2);
        const uint32_t klc = kl_s + cur * (KVBUF * 2);
        const uint32_t vhc = vh_s + cur * (KVBUF * 2);
        const uint32_t vlc = vl_s + cur * (KVBUF * 2);
        const float* Mkc = Mk + cur * 64;

        const bool more = (t + 1 < S_ / 64);
        if (more) {
            issue_tile(t + 1, 1 - cur);
            if (tid < 64) mreg = mb[(t + 1) * 64 + tid];
        }

        // ---- GEMM1: S = Q.K^T (register Q fragments, LDSM K) ----
        float accS[8][4];
#pragma unroll
        for (int nt = 0; nt < 8; nt++)
#pragma unroll
            for (int j = 0; j < 4; j++) accS[nt][j] = 0.0f;

#pragma unroll
        for (int ks = 0; ks < 4; ks++) {
#pragma unroll
            for (int np = 0; np < 4; np++) {
                uint32_t b_h[4], b_l[4];
                ldsm4(b_h, khc + np * (16 * ROWB) + 32 * ks);
                ldsm4(b_l, klc + np * (16 * ROWB) + 32 * ks);
                mma3(accS[2 * np],     aQh[ks], aQl[ks], b_h[0], b_h[1], b_l[0], b_l[1]);
                mma3(accS[2 * np + 1], aQh[ks], aQl[ks], b_h[2], b_h[3], b_l[2], b_l[3]);
            }
        }

        // ---- mask + online softmax (warp-local rows r0, r1) ----
        float ml0 = -CUDART_INF_F, ml1 = -CUDART_INF_F;
#pragma unroll
        for (int nt = 0; nt < 8; nt++) {
            const int c0 = 8 * nt + 2 * tq, c1 = c0 + 1;
            if (Mkc[c0] != 0.0f) { accS[nt][0] = -1e9f; accS[nt][2] = -1e9f; }
            if (Mkc[c1] != 0.0f) { accS[nt][1] = -1e9f; accS[nt][3] = -1e9f; }
            ml0 = fmaxf(ml0, fmaxf(accS[nt][0], accS[nt][1]));
            ml1 = fmaxf(ml1, fmaxf(accS[nt][2], accS[nt][3]));
        }
        ml0 = fmaxf(ml0, __shfl_xor_sync(0xffffffffu, ml0, 1));
        ml0 = fmaxf(ml0, __shfl_xor_sync(0xffffffffu, ml0, 2));
        ml1 = fmaxf(ml1, __shfl_xor_sync(0xffffffffu, ml1, 1));
        ml1 = fmaxf(ml1, __shfl_xor_sync(0xffffffffu, ml1, 2));

        const float mn0 = fmaxf(m0r, ml0);
        const float mn1 = fmaxf(m1r, ml1);
        const float al0 = __expf(m0r - mn0);   // 0 on first tile
        const float al1 = __expf(m1r - mn1);
        m0r = mn0; m1r = mn1;

        // P fragments built DIRECTLY in registers (acc layout == A layout)
        uint32_t aPh[4][4], aPl[4][4];
        float ls0 = 0.0f, ls1 = 0.0f;
#pragma unroll
        for (int nt = 0; nt < 8; nt++) {
            float p00 = __expf(accS[nt][0] - mn0);
            float p01 = __expf(accS[nt][1] - mn0);
            float p10 = __expf(accS[nt][2] - mn1);
            float p11 = __expf(accS[nt][3] - mn1);
            ls0 += p00 + p01;
            ls1 += p10 + p11;
            __nv_bfloat16 h00,l00,h01,l01,h10,l10,h11,l11;
            split_bf16(p00, h00, l00); split_bf16(p01, h01, l01);
            split_bf16(p10, h10, l10); split_bf16(p11, h11, l11);
            const int ks = nt >> 1;
            const int fo = (nt & 1) * 2;   // 0 -> a0/a1, 1 -> a2/a3
            aPh[ks][fo + 0] = bpack(h00, h01);
            aPh[ks][fo + 1] = bpack(h10, h11);
            aPl[ks][fo + 0] = bpack(l00, l01);
            aPl[ks][fo + 1] = bpack(l10, l11);
            accO[nt][0] *= al0; accO[nt][1] *= al0;
            accO[nt][2] *= al1; accO[nt][3] *= al1;
        }
        ls0 += __shfl_xor_sync(0xffffffffu, ls0, 1);
        ls0 += __shfl_xor_sync(0xffffffffu, ls0, 2);
        ls1 += __shfl_xor_sync(0xffffffffu, ls1, 1);
        ls1 += __shfl_xor_sync(0xffffffffu, ls1, 2);
        l0r = l0r * al0 + ls0;
        l1r = l1r * al1 + ls1;

        // ---- GEMM2: O += P.V (register-resident P fragments) ----
#pragma unroll
        for (int ks = 0; ks < 4; ks++) {
#pragma unroll
            for (int np = 0; np < 4; np++) {
                uint32_t b_h[4], b_l[4];
                ldsm4(b_h, vhc + np * (16 * ROWB) + 32 * ks);
                ldsm4(b_l, vlc + np * (16 * ROWB) + 32 * ks);
                mma3(accO[2 * np],     aPh[ks], aPl[ks], b_h[0], b_h[1], b_l[0], b_l[1]);
                mma3(accO[2 * np + 1], aPh[ks], aPl[ks], b_h[2], b_h[3], b_l[2], b_l[3]);
            }
        }

        if (more) {
            CP_WAIT0();
            if (tid < 64) Mk[(1 - cur) * 64 + tid] = (float)mreg;
        }
        __syncthreads();
    }

    // ---- epilogue: normalize + bf16-split, write att planes ----
    const float inv0 = 1.0f / l0r, inv1 = 1.0f / l1r;
#pragma unroll
    for (int nt = 0; nt < 8; nt++) {
        const int col = hh * DH_ + 8 * nt + 2 * tq;
        const size_t i0 = ((size_t)b * S_ + q0 + r0) * (H_ * DH_) + col;
        const size_t i1 = ((size_t)b * S_ + q0 + r1) * (H_ * DH_) + col;
        __nv_bfloat16 h0,l0,h1,l1;
        split_bf16(accO[nt][0] * inv0, h0, l0);
        split_bf16(accO[nt][1] * inv0, h1, l1);
        *(uint32_t*)(atthi + i0) = bpack(h0, h1);
        *(uint32_t*)(attlo + i0) = bpack(l0, l1);
        split_bf16(accO[nt][2] * inv1, h0, l0);
        split_bf16(accO[nt][3] * inv1, h1, l1);
        *(uint32_t*)(atthi + i1) = bpack(h0, h1);
        *(uint32_t*)(attlo + i1) = bpack(l0, l1);
    }
}

// ---------------------------------------------------------------------------
// kernel_launch — inputs: h, Wq, bq, Wk, bk, Wv, bv, Wo, bo, att_mask
// ---------------------------------------------------------------------------
extern "C" void kernel_launch(void* const* d_in, const int* in_sizes, int n_in,
                              void* d_out, int out_size)
{
    const float* h_in = (const float*)d_in[0];
    const float* Wq   = (const float*)d_in[1];
    const float* bq   = (const float*)d_in[2];
    const float* Wk   = (const float*)d_in[3];
    const float* bk   = (const float*)d_in[4];
    const float* Wv   = (const float*)d_in[5];
    const float* bv   = (const float*)d_in[6];
    const float* Wo   = (const float*)d_in[7];
    const float* bo   = (const float*)d_in[8];
    const int*   msk  = (const int*)d_in[9];
    float* out = (float*)d_out;

    float *qp;
    __nv_bfloat16 *hh, *hl, *wh, *wl, *khp, *klp, *vhp, *vlp, *ath, *atl;
    cudaGetSymbolAddress((void**)&qp,  g_q);
    cudaGetSymbolAddress((void**)&hh,  g_hhi);
    cudaGetSymbolAddress((void**)&hl,  g_hlo);
    cudaGetSymbolAddress((void**)&wh,  g_whi);
    cudaGetSymbolAddress((void**)&wl,  g_wlo);
    cudaGetSymbolAddress((void**)&khp, g_khi);
    cudaGetSymbolAddress((void**)&klp, g_klo);
    cudaGetSymbolAddress((void**)&vhp, g_vthi);
    cudaGetSymbolAddress((void**)&vlp, g_vtlo);
    cudaGetSymbolAddress((void**)&ath, g_atthi);
    cudaGetSymbolAddress((void**)&atl, g_attlo);

    cudaFuncSetAttribute(qkv_mma_kernel,
                         cudaFuncAttributeMaxDynamicSharedMemorySize,
                         PROJ_SMEM_BYTES);
    cudaFuncSetAttribute(proj_mma_kernel,
                         cudaFuncAttributeMaxDynamicSharedMemorySize,
                         PROJ_SMEM_BYTES);
    cudaFuncSetAttribute(attn_mma_kernel,
                         cudaFuncAttributeMaxDynamicSharedMemorySize,
                         ATTN_SMEM_BYTES);

    // fused one-shot split of h + all 4 weight matrices (single launch)
    split_all_kernel<<<(NTOT_ / 4 + 255) / 256, 256>>>(
        h_in, Wq, Wk, Wv, Wo, hh, hl, wh, wl);

    // fused Q/K/V projection: one launch, gridDim.z selects the matrix
    qkv_mma_kernel<<<dim3(D_ / 64, MROWS / 128, 3), 256, PROJ_SMEM_BYTES>>>(
        hh, hl, wh, wl, bq, bk, bv, qp, khp, klp, vhp, vlp);

    attn_mma_kernel<<<dim3(S_ / 128, B_ * H_), 256, ATTN_SMEM_BYTES>>>(
        qp, khp, klp, vhp, vlp, msk, ath, atl);

    proj_mma_kernel<<<dim3(D_ / 64, MROWS / 128), 256, PROJ_SMEM_BYTES>>>(
        ath, atl, wh + 3 * (size_t)NW_, wl + 3 * (size_t)NW_, bo, out);
}

// round 17
// speedup vs baseline: 1.0545x; 1.0545x over previous
#include <cuda_runtime.h>
#include <cuda_bf16.h>
#include <math_constants.h>
#include <cstdint>

// Problem shape (fixed)
#define B_  2
#define S_  4096
#define D_  768
#define H_  12
#define DH_ 64
#define MROWS (B_ * S_)          // 8192

// Scratch (allocation-free __device__ globals)
__device__ float g_q[B_ * H_ * S_ * DH_];
__device__ __align__(16) __nv_bfloat16 g_hhi [MROWS * D_];
__device__ __align__(16) __nv_bfloat16 g_hlo [MROWS * D_];
__device__ __align__(16) __nv_bfloat16 g_whi [4 * D_ * D_];   // Wq,Wk,Wv,Wo
__device__ __align__(16) __nv_bfloat16 g_wlo [4 * D_ * D_];
__device__ __align__(16) __nv_bfloat16 g_khi [B_ * H_ * S_ * DH_];
__device__ __align__(16) __nv_bfloat16 g_klo [B_ * H_ * S_ * DH_];
__device__ __align__(16) __nv_bfloat16 g_vthi[B_ * H_ * S_ * DH_];
__device__ __align__(16) __nv_bfloat16 g_vtlo[B_ * H_ * S_ * DH_];
__device__ __align__(16) __nv_bfloat16 g_atthi[MROWS * D_];
__device__ __align__(16) __nv_bfloat16 g_attlo[MROWS * D_];

// ---------------------------------------------------------------------------
// bf16 3-term decomposition helpers
// ---------------------------------------------------------------------------
__device__ __forceinline__ void split_bf16(float x, __nv_bfloat16& h, __nv_bfloat16& l) {
    h = __float2bfloat16_rn(x);
    l = __float2bfloat16_rn(x - __bfloat162float(h));
}
__device__ __forceinline__ uint32_t bpack(__nv_bfloat16 a, __nv_bfloat16 b) {
    return (uint32_t)__bfloat16_as_ushort(a) | ((uint32_t)__bfloat16_as_ushort(b) << 16);
}
__device__ __forceinline__ void mma16(float c[4], const uint32_t a[4],
                                      uint32_t b0, uint32_t b1) {
    asm volatile(
        "mma.sync.aligned.m16n8k16.row.col.f32.bf16.bf16.f32 "
        "{%0,%1,%2,%3}, {%4,%5,%6,%7}, {%8,%9}, {%0,%1,%2,%3};"
        : "+f"(c[0]), "+f"(c[1]), "+f"(c[2]), "+f"(c[3])
        : "r"(a[0]), "r"(a[1]), "r"(a[2]), "r"(a[3]), "r"(b0), "r"(b1));
}
__device__ __forceinline__ void mma3(float c[4],
                                     const uint32_t ah[4], const uint32_t al[4],
                                     uint32_t bh0, uint32_t bh1,
                                     uint32_t bl0, uint32_t bl1) {
    mma16(c, ah, bh0, bh1);
    mma16(c, ah, bl0, bl1);
    mma16(c, al, bh0, bh1);
}

// ldmatrix x4: four 8x8 b16 matrices; lane l supplies row (l&7) of matrix l>>3.
__device__ __forceinline__ void ldsm4(uint32_t r[4], uint32_t addr) {
    asm volatile("ldmatrix.sync.aligned.m8n8.x4.shared.b16 {%0,%1,%2,%3}, [%4];"
                 : "=r"(r[0]), "=r"(r[1]), "=r"(r[2]), "=r"(r[3]) : "r"(addr));
}

// cp.async: 16B gmem -> smem (LDGSTS).
__device__ __forceinline__ void cp16(__nv_bfloat16* dst, const __nv_bfloat16* src) {
    uint32_t s = (uint32_t)__cvta_generic_to_shared(dst);
    asm volatile("cp.async.cg.shared.global [%0], [%1], 16;"
                 :: "r"(s), "l"(src) : "memory");
}
#define CP_COMMIT() asm volatile("cp.async.commit_group;" ::: "memory")
#define CP_WAIT0()  asm volatile("cp.async.wait_group 0;"  ::: "memory")

#define PADB 72      // bf16 row stride (144 B = 9*16B: LDSM conflict-free)
#define ROWB (PADB * 2)   // bytes

// ---------------------------------------------------------------------------
// Fused one-shot splitter: h + Wq + Wk + Wv + Wo -> bf16 hi/lo planes.
// ---------------------------------------------------------------------------
#define NH_ (MROWS * D_)     // 6291456
#define NW_ (D_ * D_)        // 589824
#define NTOT_ (NH_ + 4 * NW_)

__device__ __forceinline__ void split4(const float* __restrict__ src,
                                       __nv_bfloat16* __restrict__ hi,
                                       __nv_bfloat16* __restrict__ lo, int i)
{
    float4 v = *(const float4*)(src + i);
    __nv_bfloat16 h0,l0,h1,l1,h2,l2,h3,l3;
    split_bf16(v.x, h0, l0); split_bf16(v.y, h1, l1);
    split_bf16(v.z, h2, l2); split_bf16(v.w, h3, l3);
    *(uint32_t*)(hi + i)     = bpack(h0, h1);
    *(uint32_t*)(hi + i + 2) = bpack(h2, h3);
    *(uint32_t*)(lo + i)     = bpack(l0, l1);
    *(uint32_t*)(lo + i + 2) = bpack(l2, l3);
}

__global__ void split_all_kernel(
    const float* __restrict__ h,
    const float* __restrict__ Wq, const float* __restrict__ Wk,
    const float* __restrict__ Wv, const float* __restrict__ Wo,
    __nv_bfloat16* __restrict__ hhi, __nv_bfloat16* __restrict__ hlo,
    __nv_bfloat16* __restrict__ whi, __nv_bfloat16* __restrict__ wlo)
{
    const int gi = (blockIdx.x * blockDim.x + threadIdx.x) * 4;
    if (gi >= NTOT_) return;
    if (gi < NH_) {
        split4(h, hhi, hlo, gi);
    } else {
        const int wi = gi - NH_;
        const int z  = wi / NW_;             // 0..3 (all 4 ranges NW_-aligned)
        const int li = wi - z * NW_;
        const float* src = (z == 0) ? Wq : (z == 1) ? Wk : (z == 2) ? Wv : Wo;
        split4(src, whi + (size_t)z * NW_, wlo + (size_t)z * NW_, li);
    }
}

// ---------------------------------------------------------------------------
// Shared projection GEMM body (NT), bf16 3-term, cp.async double-buffered,
// LDSM fragments SOFTWARE-PIPELINED: iteration i issues the LDSMs for i+1
// before its MMAs (breaks the LDSM->HMMA dependency that ncu showed was
// stalling the tensor pipe at 35%).
// ---------------------------------------------------------------------------
#define ABUF (128 * PADB)
#define WBUF (64 * PADB)
#define PROJ_SMEM_BYTES ((2 * ABUF + 2 * WBUF) * 2 * 2)

__device__ __forceinline__ void proj_body(
    const __nv_bfloat16* __restrict__ Ahg, const __nv_bfloat16* __restrict__ Alg,
    const __nv_bfloat16* __restrict__ Whg, const __nv_bfloat16* __restrict__ Wlg,
    const float* __restrict__ bias,
    float* __restrict__ Cf,
    __nv_bfloat16* __restrict__ Chi, __nv_bfloat16* __restrict__ Clo,
    int K, int mode, float scale, __nv_bfloat16* smb)
{
    __nv_bfloat16* Ah = smb;                 // [2][ABUF]
    __nv_bfloat16* Al = Ah + 2 * ABUF;
    __nv_bfloat16* Wh = Al + 2 * ABUF;       // [2][WBUF]
    __nv_bfloat16* Wl = Wh + 2 * WBUF;

    const int tid  = threadIdx.x;
    const int mw   = tid >> 5;
    const int lane = tid & 31;
    const int quad = lane >> 2;
    const int tq   = lane & 3;
    const int m0 = blockIdx.y * 128;
    const int n0 = blockIdx.x * 64;

    const int r0 = 16 * mw + quad;
    const int r1 = r0 + 8;

    const int arow = tid >> 1, aseg = (tid & 1) * 32;
    const int wrow = tid >> 2, wseg = (tid & 3) * 16;
    const int adst = arow * PADB + aseg;
    const int wdst = wrow * PADB + wseg;
    const __nv_bfloat16* ahs = Ahg + (size_t)(m0 + arow) * K + aseg;
    const __nv_bfloat16* als = Alg + (size_t)(m0 + arow) * K + aseg;
    const __nv_bfloat16* whs = Whg + (size_t)(n0 + wrow) * K + wseg;
    const __nv_bfloat16* wls = Wlg + (size_t)(n0 + wrow) * K + wseg;

    auto issue_chunk = [&](int kc, int bsel) {
#pragma unroll
        for (int u = 0; u < 4; u++) {
            cp16(Ah + bsel * ABUF + adst + 8 * u, ahs + kc + 8 * u);
            cp16(Al + bsel * ABUF + adst + 8 * u, als + kc + 8 * u);
        }
#pragma unroll
        for (int u = 0; u < 2; u++) {
            cp16(Wh + bsel * WBUF + wdst + 8 * u, whs + kc + 8 * u);
            cp16(Wl + bsel * WBUF + wdst + 8 * u, wls + kc + 8 * u);
        }
        CP_COMMIT();
    };

    const int g = lane >> 3, r8 = lane & 7;
    const uint32_t offA = (uint32_t)((16 * mw + (g & 1) * 8 + r8) * ROWB + (g >> 1) * 16);
    const uint32_t offB = (uint32_t)(((g >> 1) * 8 + r8) * ROWB + (g & 1) * 16);
    const uint32_t ah_s = (uint32_t)__cvta_generic_to_shared(Ah) + offA;
    const uint32_t al_s = (uint32_t)__cvta_generic_to_shared(Al) + offA;
    const uint32_t wh_s = (uint32_t)__cvta_generic_to_shared(Wh) + offB;
    const uint32_t wl_s = (uint32_t)__cvta_generic_to_shared(Wl) + offB;

    float accC[8][4];
#pragma unroll
    for (int nt = 0; nt < 8; nt++)
#pragma unroll
        for (int j = 0; j < 4; j++) accC[nt][j] = 0.0f;

    issue_chunk(0, 0);
    CP_WAIT0();
    __syncthreads();

    const int NCH = K / 64;
    for (int t = 0; t < NCH; t++) {
        const int cur = t & 1;
        const uint32_t ac = ah_s + cur * (ABUF * 2);
        const uint32_t lc = al_s + cur * (ABUF * 2);
        const uint32_t wc = wh_s + cur * (WBUF * 2);
        const uint32_t xc = wl_s + cur * (WBUF * 2);

        const bool more = (t + 1 < NCH);
        if (more) issue_chunk((t + 1) * 64, 1 - cur);

        // pipelined MMA loop: 16 steps (ks=it>>2, np=it&3), B double-buffered,
        // A double-buffered per-ks (prefetched at np==0 of previous ks).
        uint32_t a_h[2][4], a_l[2][4], b_h[2][4], b_l[2][4];
        ldsm4(a_h[0], ac);  ldsm4(a_l[0], lc);
        ldsm4(b_h[0], wc);  ldsm4(b_l[0], xc);
#pragma unroll
        for (int it = 0; it < 16; it++) {
            const int ks = it >> 2, np = it & 3;
            const int bb = it & 1, ab = ks & 1;
            if (np == 0 && ks < 3) {             // prefetch next ks's A frags
                ldsm4(a_h[ab ^ 1], ac + 32 * (ks + 1));
                ldsm4(a_l[ab ^ 1], lc + 32 * (ks + 1));
            }
            if (it < 15) {                        // prefetch next B frags
                const int ks1 = (it + 1) >> 2, np1 = (it + 1) & 3;
                ldsm4(b_h[bb ^ 1], wc + np1 * (16 * ROWB) + 32 * ks1);
                ldsm4(b_l[bb ^ 1], xc + np1 * (16 * ROWB) + 32 * ks1);
            }
            mma3(accC[2 * np],     a_h[ab], a_l[ab],
                 b_h[bb][0], b_h[bb][1], b_l[bb][0], b_l[bb][1]);
            mma3(accC[2 * np + 1], a_h[ab], a_l[ab],
                 b_h[bb][2], b_h[bb][3], b_l[bb][2], b_l[bb][3]);
        }

        if (more) CP_WAIT0();
        __syncthreads();
    }

    // epilogue
#pragma unroll
    for (int nt = 0; nt < 8; nt++) {
        const int n = n0 + 8 * nt + 2 * tq;
        const float b0v = bias[n], b1v = bias[n + 1];
#pragma unroll
        for (int half = 0; half < 2; half++) {
            const int m = m0 + (half ? r1 : r0);
            float v0 = (accC[nt][2 * half + 0] + b0v) * scale;
            float v1 = (accC[nt][2 * half + 1] + b1v) * scale;
            if (mode == 0) {
                *(float2*)(Cf + (size_t)m * D_ + n) = make_float2(v0, v1);
            } else {
                const int bb = m >> 12, s = m & (S_ - 1);
                const int hh = n >> 6,  d = n & (DH_ - 1);
                if (mode == 1) {
                    const size_t idx = (((size_t)bb * H_ + hh) * S_ + s) * DH_ + d;
                    *(float2*)(Cf + idx) = make_float2(v0, v1);
                } else if (mode == 2) {
                    const size_t idx = (((size_t)bb * H_ + hh) * S_ + s) * DH_ + d;
                    __nv_bfloat16 h0,l0,h1,l1;
                    split_bf16(v0, h0, l0); split_bf16(v1, h1, l1);
                    *(uint32_t*)(Chi + idx) = bpack(h0, h1);
                    *(uint32_t*)(Clo + idx) = bpack(l0, l1);
                } else {   // mode 3: transposed [B,H,DH,S]
                    const size_t tix = (((size_t)bb * H_ + hh) * DH_ + d) * S_ + s;
                    __nv_bfloat16 h0,l0,h1,l1;
                    split_bf16(v0, h0, l0); split_bf16(v1, h1, l1);
                    Chi[tix] = h0; Chi[tix + S_] = h1;
                    Clo[tix] = l0; Clo[tix + S_] = l1;
                }
            }
        }
    }
}

// Fused QKV projection: gridDim.z = 3 selects Q/K/V (shared A = split h).
__global__ __launch_bounds__(256) void qkv_mma_kernel(
    const __nv_bfloat16* __restrict__ Ahg, const __nv_bfloat16* __restrict__ Alg,
    const __nv_bfloat16* __restrict__ Wall_h, const __nv_bfloat16* __restrict__ Wall_l,
    const float* __restrict__ bq, const float* __restrict__ bk,
    const float* __restrict__ bv,
    float* __restrict__ qout,
    __nv_bfloat16* __restrict__ khi, __nv_bfloat16* __restrict__ klo,
    __nv_bfloat16* __restrict__ vhi, __nv_bfloat16* __restrict__ vlo)
{
    extern __shared__ __nv_bfloat16 smb[];
    const int z = blockIdx.z;
    const __nv_bfloat16* Wh = Wall_h + (size_t)z * NW_;
    const __nv_bfloat16* Wl = Wall_l + (size_t)z * NW_;
    const float* bias = (z == 0) ? bq : (z == 1) ? bk : bv;
    float* Cf = (z == 0) ? qout : nullptr;
    __nv_bfloat16* Chi = (z == 1) ? khi : (z == 2) ? vhi : nullptr;
    __nv_bfloat16* Clo = (z == 1) ? klo : (z == 2) ? vlo : nullptr;
    const int mode = z + 1;
    const float scale = (z == 0) ? 0.125f : 1.0f;
    proj_body(Ahg, Alg, Wh, Wl, bias, Cf, Chi, Clo, D_, mode, scale, smb);
}

// Output projection (Wo), mode 0.
__global__ __launch_bounds__(256) void proj_mma_kernel(
    const __nv_bfloat16* __restrict__ Ahg, const __nv_bfloat16* __restrict__ Alg,
    const __nv_bfloat16* __restrict__ Whg, const __nv_bfloat16* __restrict__ Wlg,
    const float* __restrict__ bias, float* __restrict__ Cf)
{
    extern __shared__ __nv_bfloat16 smb[];
    proj_body(Ahg, Alg, Whg, Wlg, bias, Cf, nullptr, nullptr, D_, 0, 1.0f, smb);
}

// ---------------------------------------------------------------------------
// Flash attention, bf16 3-term, cp.async double-buffered K/V, LDSM fragments.
// P and Q fragments REGISTER-RESIDENT. B-fragment LDSMs software-pipelined;
// first V fragments prefetched before the softmax block (ALU hides latency).
// ---------------------------------------------------------------------------
#define KVBUF (64 * PADB)
#define ATTN_SMEM_BYTES ((2*128*PADB + 8*KVBUF) * 2 + 2 * 64 * 4)

__global__ __launch_bounds__(256) void attn_mma_kernel(
    const float* __restrict__ q,
    const __nv_bfloat16* __restrict__ khi, const __nv_bfloat16* __restrict__ klo,
    const __nv_bfloat16* __restrict__ vthi, const __nv_bfloat16* __restrict__ vtlo,
    const int* __restrict__ mask,
    __nv_bfloat16* __restrict__ atthi, __nv_bfloat16* __restrict__ attlo)
{
    extern __shared__ __nv_bfloat16 smb[];
    __nv_bfloat16* Qh = smb;                       // [128][PADB]
    __nv_bfloat16* Ql = Qh + 128 * PADB;
    __nv_bfloat16* Kh = Ql + 128 * PADB;           // [2][64][PADB]
    __nv_bfloat16* Kl = Kh + 2 * KVBUF;
    __nv_bfloat16* Vh = Kl + 2 * KVBUF;            // [2][64][PADB] (transposed)
    __nv_bfloat16* Vl = Vh + 2 * KVBUF;
    float* Mk = (float*)(Vl + 2 * KVBUF);          // [2][64]

    const int tid  = threadIdx.x;
    const int mw   = tid >> 5;
    const int lane = tid & 31;
    const int quad = lane >> 2;
    const int tq   = lane & 3;
    const int bh = blockIdx.y;
    const int b  = bh / H_;
    const int hh = bh - b * H_;
    const int q0 = blockIdx.x * 128;

    const size_t hoff = (size_t)bh * S_ * DH_;
    const float* qb = q + hoff;
    const int*   mb = mask + b * S_;

    const int r0 = 16 * mw + quad;
    const int r1 = r0 + 8;

    const int lrow8 = 8 * mw + (lane & 7);
    const int lseg  = (lane >> 3) * 16;
    const int sdst  = lrow8 * PADB + lseg;
    const __nv_bfloat16* khg = khi  + hoff + (size_t)lrow8 * DH_ + lseg;
    const __nv_bfloat16* klg = klo  + hoff + (size_t)lrow8 * DH_ + lseg;
    const __nv_bfloat16* vhg = vthi + hoff + (size_t)lrow8 * S_ + lseg;
    const __nv_bfloat16* vlg = vtlo + hoff + (size_t)lrow8 * S_ + lseg;

    auto issue_tile = [&](int t, int bsel) {
        const size_t ko = (size_t)t * 64 * DH_;
        const size_t vo = (size_t)t * 64;
        cp16(Kh + bsel * KVBUF + sdst,     khg + ko);
        cp16(Kh + bsel * KVBUF + sdst + 8, khg + ko + 8);
        cp16(Kl + bsel * KVBUF + sdst,     klg + ko);
        cp16(Kl + bsel * KVBUF + sdst + 8, klg + ko + 8);
        cp16(Vh + bsel * KVBUF + sdst,     vhg + vo);
        cp16(Vh + bsel * KVBUF + sdst + 8, vhg + vo + 8);
        cp16(Vl + bsel * KVBUF + sdst,     vlg + vo);
        cp16(Vl + bsel * KVBUF + sdst + 8, vlg + vo + 8);
        CP_COMMIT();
    };

    // LDSM per-lane offsets
    const int g = lane >> 3, r8 = lane & 7;
    const uint32_t offA = (uint32_t)((16 * mw + (g & 1) * 8 + r8) * ROWB + (g >> 1) * 16);
    const uint32_t offB = (uint32_t)(((g >> 1) * 8 + r8) * ROWB + (g & 1) * 16);
    const uint32_t qh_s = (uint32_t)__cvta_generic_to_shared(Qh) + offA;
    const uint32_t ql_s = (uint32_t)__cvta_generic_to_shared(Ql) + offA;
    const uint32_t kh_s = (uint32_t)__cvta_generic_to_shared(Kh) + offB;
    const uint32_t kl_s = (uint32_t)__cvta_generic_to_shared(Kl) + offB;
    const uint32_t vh_s = (uint32_t)__cvta_generic_to_shared(Vh) + offB;
    const uint32_t vl_s = (uint32_t)__cvta_generic_to_shared(Vl) + offB;

    issue_tile(0, 0);
    int mreg = (tid < 64) ? mb[tid] : 0;
    {
        const int row = tid >> 1, colb = (tid & 1) * 32;
#pragma unroll
        for (int u = 0; u < 8; u++) {
            const int c = colb + 4 * u;
            float4 qv = *(const float4*)(qb + (size_t)(q0 + row) * DH_ + c);
            __nv_bfloat16 h0,l0,h1,l1,h2,l2,h3,l3;
            split_bf16(qv.x, h0, l0); split_bf16(qv.y, h1, l1);
            split_bf16(qv.z, h2, l2); split_bf16(qv.w, h3, l3);
            *(uint32_t*)(Qh + row * PADB + c)     = bpack(h0, h1);
            *(uint32_t*)(Qh + row * PADB + c + 2) = bpack(h2, h3);
            *(uint32_t*)(Ql + row * PADB + c)     = bpack(l0, l1);
            *(uint32_t*)(Ql + row * PADB + c + 2) = bpack(l2, l3);
        }
    }
    CP_WAIT0();
    if (tid < 64) Mk[tid] = (float)mreg;   // Mk[0]
    __syncthreads();

    // ---- hoist Q fragments into registers (loop-invariant) ----
    uint32_t aQh[4][4], aQl[4][4];
#pragma unroll
    for (int ks = 0; ks < 4; ks++) {
        ldsm4(aQh[ks], qh_s + 32 * ks);
        ldsm4(aQl[ks], ql_s + 32 * ks);
    }

    float m0r = -CUDART_INF_F, m1r = -CUDART_INF_F;
    float l0r = 0.0f, l1r = 0.0f;
    float accO[8][4];
#pragma unroll
    for (int nt = 0; nt < 8; nt++)
#pragma unroll
        for (int j = 0; j < 4; j++) accO[nt][j] = 0.0f;

    for (int t = 0; t < S_ / 64; t++) {
        const int cur = t & 1;
        const uint32_t khc = kh_s + cur * (KVBUF * 2);
        const uint32_t klc = kl_s + cur * (KVBUF * 2);
        const uint32_t vhc = vh_s + cur * (KVBUF * 2);
        const uint32_t vlc = vl_s + cur * (KVBUF * 2);
        const float* Mkc = Mk + cur * 64;

        const bool more = (t + 1 < S_ / 64);
        if (more) {
            issue_tile(t + 1, 1 - cur);
            if (tid < 64) mreg = mb[(t + 1) * 64 + tid];
        }

        // ---- GEMM1: S = Q.K^T (register Q frags, pipelined K frags) ----
        float accS[8][4];
#pragma unroll
        for (int nt = 0; nt < 8; nt++)
#pragma unroll
            for (int j = 0; j < 4; j++) accS[nt][j] = 0.0f;

        uint32_t b_h[2][4], b_l[2][4];
        ldsm4(b_h[0], khc);  ldsm4(b_l[0], klc);
#pragma unroll
        for (int it = 0; it < 16; it++) {
            const int ks = it >> 2, np = it & 3;
            const int bb = it & 1;
            if (it < 15) {
                const int ks1 = (it + 1) >> 2, np1 = (it + 1) & 3;
                ldsm4(b_h[bb ^ 1], khc + np1 * (16 * ROWB) + 32 * ks1);
                ldsm4(b_l[bb ^ 1], klc + np1 * (16 * ROWB) + 32 * ks1);
            }
            mma3(accS[2 * np],     aQh[ks], aQl[ks],
                 b_h[bb][0], b_h[bb][1], b_l[bb][0], b_l[bb][1]);
            mma3(accS[2 * np + 1], aQh[ks], aQl[ks],
                 b_h[bb][2], b_h[bb][3], b_l[bb][2], b_l[bb][3]);
        }

        // prefetch first V fragments: softmax ALU below hides their latency
        ldsm4(b_h[0], vhc);  ldsm4(b_l[0], vlc);

        // ---- mask + online softmax (warp-local rows r0, r1) ----
        float ml0 = -CUDART_INF_F, ml1 = -CUDART_INF_F;
#pragma unroll
        for (int nt = 0; nt < 8; nt++) {
            const int c0 = 8 * nt + 2 * tq, c1 = c0 + 1;
            if (Mkc[c0] != 0.0f) { accS[nt][0] = -1e9f; accS[nt][2] = -1e9f; }
            if (Mkc[c1] != 0.0f) { accS[nt][1] = -1e9f; accS[nt][3] = -1e9f; }
            ml0 = fmaxf(ml0, fmaxf(accS[nt][0], accS[nt][1]));
            ml1 = fmaxf(ml1, fmaxf(accS[nt][2], accS[nt][3]));
        }
        ml0 = fmaxf(ml0, __shfl_xor_sync(0xffffffffu, ml0, 1));
        ml0 = fmaxf(ml0, __shfl_xor_sync(0xffffffffu, ml0, 2));
        ml1 = fmaxf(ml1, __shfl_xor_sync(0xffffffffu, ml1, 1));
        ml1 = fmaxf(ml1, __shfl_xor_sync(0xffffffffu, ml1, 2));

        const float mn0 = fmaxf(m0r, ml0);
        const float mn1 = fmaxf(m1r, ml1);
        const float al0 = __expf(m0r - mn0);   // 0 on first tile
        const float al1 = __expf(m1r - mn1);
        m0r = mn0; m1r = mn1;

        // P fragments built DIRECTLY in registers (acc layout == A layout)
        uint32_t aPh[4][4], aPl[4][4];
        float ls0 = 0.0f, ls1 = 0.0f;
#pragma unroll
        for (int nt = 0; nt < 8; nt++) {
            float p00 = __expf(accS[nt][0] - mn0);
            float p01 = __expf(accS[nt][1] - mn0);
            float p10 = __expf(accS[nt][2] - mn1);
            float p11 = __expf(accS[nt][3] - mn1);
            ls0 += p00 + p01;
            ls1 += p10 + p11;
            __nv_bfloat16 h00,l00,h01,l01,h10,l10,h11,l11;
            split_bf16(p00, h00, l00); split_bf16(p01, h01, l01);
            split_bf16(p10, h10, l10); split_bf16(p11, h11, l11);
            const int ks = nt >> 1;
            const int fo = (nt & 1) * 2;   // 0 -> a0/a1, 1 -> a2/a3
            aPh[ks][fo + 0] = bpack(h00, h01);
            aPh[ks][fo + 1] = bpack(h10, h11);
            aPl[ks][fo + 0] = bpack(l00, l01);
            aPl[ks][fo + 1] = bpack(l10, l11);
            accO[nt][0] *= al0; accO[nt][1] *= al0;
            accO[nt][2] *= al1; accO[nt][3] *= al1;
        }
        ls0 += __shfl_xor_sync(0xffffffffu, ls0, 1);
        ls0 += __shfl_xor_sync(0xffffffffu, ls0, 2);
        ls1 += __shfl_xor_sync(0xffffffffu, ls1, 1);
        ls1 += __shfl_xor_sync(0xffffffffu, ls1, 2);
        l0r = l0r * al0 + ls0;
        l1r = l1r * al1 + ls1;

        // ---- GEMM2: O += P.V (register P frags, pipelined V frags) ----
#pragma unroll
        for (int it = 0; it < 16; it++) {
            const int ks = it >> 2, np = it & 3;
            const int bb = it & 1;
            if (it < 15) {
                const int ks1 = (it + 1) >> 2, np1 = (it + 1) & 3;
                ldsm4(b_h[bb ^ 1], vhc + np1 * (16 * ROWB) + 32 * ks1);
                ldsm4(b_l[bb ^ 1], vlc + np1 * (16 * ROWB) + 32 * ks1);
            }
            mma3(accO[2 * np],     aPh[ks], aPl[ks],
                 b_h[bb][0], b_h[bb][1], b_l[bb][0], b_l[bb][1]);
            mma3(accO[2 * np + 1], aPh[ks], aPl[ks],
                 b_h[bb][2], b_h[bb][3], b_l[bb][2], b_l[bb][3]);
        }

        if (more) {
            CP_WAIT0();
            if (tid < 64) Mk[(1 - cur) * 64 + tid] = (float)mreg;
        }
        __syncthreads();
    }

    // ---- epilogue: normalize + bf16-split, write att planes ----
    const float inv0 = 1.0f / l0r, inv1 = 1.0f / l1r;
#pragma unroll
    for (int nt = 0; nt < 8; nt++) {
        const int col = hh * DH_ + 8 * nt + 2 * tq;
        const size_t i0 = ((size_t)b * S_ + q0 + r0) * (H_ * DH_) + col;
        const size_t i1 = ((size_t)b * S_ + q0 + r1) * (H_ * DH_) + col;
        __nv_bfloat16 h0,l0,h1,l1;
        split_bf16(accO[nt][0] * inv0, h0, l0);
        split_bf16(accO[nt][1] * inv0, h1, l1);
        *(uint32_t*)(atthi + i0) = bpack(h0, h1);
        *(uint32_t*)(attlo + i0) = bpack(l0, l1);
        split_bf16(accO[nt][2] * inv1, h0, l0);
        split_bf16(accO[nt][3] * inv1, h1, l1);
        *(uint32_t*)(atthi + i1) = bpack(h0, h1);
        *(uint32_t*)(attlo + i1) = bpack(l0, l1);
    }
}

// ---------------------------------------------------------------------------
// kernel_launch — inputs: h, Wq, bq, Wk, bk, Wv, bv, Wo, bo, att_mask
// ---------------------------------------------------------------------------
extern "C" void kernel_launch(void* const* d_in, const int* in_sizes, int n_in,
                              void* d_out, int out_size)
{
    const float* h_in = (const float*)d_in[0];
    const float* Wq   = (const float*)d_in[1];
    const float* bq   = (const float*)d_in[2];
    const float* Wk   = (const float*)d_in[3];
    const float* bk   = (const float*)d_in[4];
    const float* Wv   = (const float*)d_in[5];
    const float* bv   = (const float*)d_in[6];
    const float* Wo   = (const float*)d_in[7];
    const float* bo   = (const float*)d_in[8];
    const int*   msk  = (const int*)d_in[9];
    float* out = (float*)d_out;

    float *qp;
    __nv_bfloat16 *hh, *hl, *wh, *wl, *khp, *klp, *vhp, *vlp, *ath, *atl;
    cudaGetSymbolAddress((void**)&qp,  g_q);
    cudaGetSymbolAddress((void**)&hh,  g_hhi);
    cudaGetSymbolAddress((void**)&hl,  g_hlo);
    cudaGetSymbolAddress((void**)&wh,  g_whi);
    cudaGetSymbolAddress((void**)&wl,  g_wlo);
    cudaGetSymbolAddress((void**)&khp, g_khi);
    cudaGetSymbolAddress((void**)&klp, g_klo);
    cudaGetSymbolAddress((void**)&vhp, g_vthi);
    cudaGetSymbolAddress((void**)&vlp, g_vtlo);
    cudaGetSymbolAddress((void**)&ath, g_atthi);
    cudaGetSymbolAddress((void**)&atl, g_attlo);

    cudaFuncSetAttribute(qkv_mma_kernel,
                         cudaFuncAttributeMaxDynamicSharedMemorySize,
                         PROJ_SMEM_BYTES);
    cudaFuncSetAttribute(proj_mma_kernel,
                         cudaFuncAttributeMaxDynamicSharedMemorySize,
                         PROJ_SMEM_BYTES);
    cudaFuncSetAttribute(attn_mma_kernel,
                         cudaFuncAttributeMaxDynamicSharedMemorySize,
                         ATTN_SMEM_BYTES);
    // max carveout so proj (110.6 KB, 72 regs) can co-reside 2 blocks/SM
    cudaFuncSetAttribute(qkv_mma_kernel,
                         cudaFuncAttributePreferredSharedMemoryCarveout, 100);
    cudaFuncSetAttribute(proj_mma_kernel,
                         cudaFuncAttributePreferredSharedMemoryCarveout, 100);
    cudaFuncSetAttribute(attn_mma_kernel,
                         cudaFuncAttributePreferredSharedMemoryCarveout, 100);

    // fused one-shot split of h + all 4 weight matrices (single launch)
    split_all_kernel<<<(NTOT_ / 4 + 255) / 256, 256>>>(
        h_in, Wq, Wk, Wv, Wo, hh, hl, wh, wl);

    // fused Q/K/V projection: one launch, gridDim.z selects the matrix
    qkv_mma_kernel<<<dim3(D_ / 64, MROWS / 128, 3), 256, PROJ_SMEM_BYTES>>>(
        hh, hl, wh, wl, bq, bk, bv, qp, khp, klp, vhp, vlp);

    attn_mma_kernel<<<dim3(S_ / 128, B_ * H_), 256, ATTN_SMEM_BYTES>>>(
        qp, khp, klp, vhp, vlp, msk, ath, atl);

    proj_mma_kernel<<<dim3(D_ / 64, MROWS / 128), 256, PROJ_SMEM_BYTES>>>(
        ath, atl, wh + 3 * (size_t)NW_, wl + 3 * (size_t)NW_, bo, out);
}